// round 16
// baseline (speedup 1.0000x reference)
#include <cuda_runtime.h>
#include <math.h>

#define HDIM 512
#define BSZ  128
#define TIN  256
#define MLEN 128
#define VOC  32
#define BH   (BSZ*HDIM)
#define B2H  (BSZ*2*HDIM)
#define NBLK 148
#define NTHR 512
#define SLW  36          // smem row width in floats (32k chunk + pad, 2-phase optimal)

typedef unsigned long long u64;

// ---------------- device scratch ----------------
__device__ float g_y0[TIN*BH];
__device__ float g_enc[TIN*BH];
__device__ float g_q[MLEN*BH];
__device__ float g_rnn[MLEN*B2H];
__device__ float g_h0[MLEN*BH];
__device__ float g_h1[MLEN*BH];
__device__ int   g_tok[(MLEN+1)*BSZ];
// raw gate-sum scratch: [gate(3)][B][H] planes
__device__ float g_ghE0[3*BH];   // encoder L0 hidden sums
__device__ float g_giE1[3*BH];   // encoder L1 input sums
__device__ float g_ghE1[3*BH];   // encoder L1 hidden sums
__device__ float g_gi0[3*BH];    // decoder gru0 input sums
__device__ float g_gh0[3*BH];    // decoder gru0 hidden sums
__device__ float g_gi1[3*BH];    // decoder gru1 input sums
__device__ float g_gh1[3*BH];    // decoder gru1 hidden sums
__device__ unsigned g_arrive;
__device__ volatile unsigned g_release;

// ---------------- shared memory ----------------
struct SmSlice { float hs[2][64][SLW]; float ws[2][48][SLW]; };  // 32256 B
struct SmA { float q[HDIM]; float sc[TIN]; float red[16]; };
struct SmL { float hrow[HDIM]; float lg[VOC]; };
union SmAll {
    SmSlice sl[4];            // 129024 B
    u64 comb[3][128][24];     // 73728 B (aliases; used only after GEMM compute done)
    SmA a;
    SmL l;
};

// ---------------- helpers ----------------
__device__ __forceinline__ u64 fma2(u64 a, u64 b, u64 c)
{
    u64 d;
    asm("fma.rn.f32x2 %0, %1, %2, %3;" : "=l"(d) : "l"(a), "l"(b), "l"(c));
    return d;
}
__device__ __forceinline__ u64 add2(u64 a, u64 b)
{
    u64 d;
    asm("add.rn.f32x2 %0, %1, %2;" : "=l"(d) : "l"(a), "l"(b));
    return d;
}
__device__ __forceinline__ float red2(u64 a)
{
    float lo, hi;
    asm("mov.b64 {%0, %1}, %2;" : "=f"(lo), "=f"(hi) : "l"(a));
    return lo + hi;
}
// named barrier for one 128-thread k-slice (ids 1..4)
__device__ __forceinline__ void barg(int slice)
{
    asm volatile("bar.sync %0, %1;" :: "r"(slice + 1), "r"(128) : "memory");
}

// ---------------- software grid barrier ----------------
__device__ __forceinline__ void gsync(unsigned &phase)
{
    __threadfence();
    __syncthreads();
    phase++;
    if (threadIdx.x == 0) {
        unsigned p = phase;
        unsigned old = atomicAdd(&g_arrive, 1u);
        if (old == p * (unsigned)NBLK - 1u) {
            g_release = p;
        } else {
            while (g_release < p) { }
        }
        __threadfence();
    }
    __syncthreads();
}

// ---------------- pipelined K-major GEMM accumulate (per 128-thread k-slice) ----------------
// Output tile: 64 rows x 16 cols x NG gates. Slice handles k in [kBase, kBase+Kh),
// 32-wide chunks, double-buffered, register-staged (LDG->reg->STS, R8-proven).
// Thread t1: cL = t1&15 (col), rG = t1>>4 (8-row group). 8 rows x NG gates accum.
template<int NG>
__device__ __forceinline__ void gemm_pipe(
    const float* __restrict__ A, int lda,
    const float* __restrict__ W, int ldw,
    int kBase, int Kh, int rowBase, int colBase,
    u64 (&a0)[8], u64 (&a1)[8], u64 (&a2)[8],
    SmSlice& sg, int slice)
{
    const int t1 = threadIdx.x & 127;
    const int cL = t1 & 15;
    const int rG = t1 >> 4;

    // h fill mapping: 512 float4 per chunk (64 rows x 8 f4), 4 per thread
    const int hr0 = (t1*4 + 0) >> 3, hk0 = ((t1*4 + 0) & 7) << 2;
    const int hr1 = (t1*4 + 1) >> 3, hk1 = ((t1*4 + 1) & 7) << 2;
    const int hr2 = (t1*4 + 2) >> 3, hk2 = ((t1*4 + 2) & 7) << 2;
    const int hr3 = (t1*4 + 3) >> 3, hk3 = ((t1*4 + 3) & 7) << 2;
    const size_t hOff0 = (size_t)(rowBase + hr0)*lda + kBase + hk0;
    const size_t hOff1 = (size_t)(rowBase + hr1)*lda + kBase + hk1;
    const size_t hOff2 = (size_t)(rowBase + hr2)*lda + kBase + hk2;
    const size_t hOff3 = (size_t)(rowBase + hr3)*lda + kBase + hk3;

    // w fill mapping: NG3: 384 f4 (48 rows x 8), 3/thread. NG1: 128 f4, 1/thread.
    int wr0, wk0, wr1 = 0, wk1 = 0, wr2 = 0, wk2 = 0;
    if (NG == 3) {
        wr0 = (t1*3 + 0) >> 3; wk0 = ((t1*3 + 0) & 7) << 2;
        wr1 = (t1*3 + 1) >> 3; wk1 = ((t1*3 + 1) & 7) << 2;
        wr2 = (t1*3 + 2) >> 3; wk2 = ((t1*3 + 2) & 7) << 2;
    } else {
        wr0 = t1 >> 3; wk0 = (t1 & 7) << 2;
    }
    const size_t wOff0 = (size_t)((wr0 >> 4)*HDIM + colBase + (wr0 & 15))*ldw + kBase + wk0;
    const size_t wOff1 = (NG == 3) ? (size_t)((wr1 >> 4)*HDIM + colBase + (wr1 & 15))*ldw + kBase + wk1 : 0;
    const size_t wOff2 = (NG == 3) ? (size_t)((wr2 >> 4)*HDIM + colBase + (wr2 & 15))*ldw + kBase + wk2 : 0;

    const int nt = Kh >> 5;
    float4 pH0, pH1, pH2, pH3, pW0, pW1, pW2;

#define GLD(kt) do { int k0_ = (kt) << 5;                               \
        pH0 = *(const float4*)(A + hOff0 + k0_);                        \
        pH1 = *(const float4*)(A + hOff1 + k0_);                        \
        pH2 = *(const float4*)(A + hOff2 + k0_);                        \
        pH3 = *(const float4*)(A + hOff3 + k0_);                        \
        pW0 = *(const float4*)(W + wOff0 + k0_);                        \
        if (NG == 3) { pW1 = *(const float4*)(W + wOff1 + k0_);         \
                       pW2 = *(const float4*)(W + wOff2 + k0_); }       \
    } while (0)
#define GST(b) do {                                                     \
        *(float4*)&sg.hs[b][hr0][hk0] = pH0;                            \
        *(float4*)&sg.hs[b][hr1][hk1] = pH1;                            \
        *(float4*)&sg.hs[b][hr2][hk2] = pH2;                            \
        *(float4*)&sg.hs[b][hr3][hk3] = pH3;                            \
        *(float4*)&sg.ws[b][wr0][wk0] = pW0;                            \
        if (NG == 3) { *(float4*)&sg.ws[b][wr1][wk1] = pW1;             \
                       *(float4*)&sg.ws[b][wr2][wk2] = pW2; }           \
    } while (0)

    GLD(0); GST(0);
    if (nt > 1) GLD(1);
    barg(slice);

    for (int kt = 0; kt < nt; kt++) {
        const int cur = kt & 1;
        if (kt + 1 < nt) GST(cur ^ 1);
        if (kt + 2 < nt) GLD(kt + 2);
        #pragma unroll
        for (int kk = 0; kk < 32; kk += 4) {
            ulonglong2 w0 = *(const ulonglong2*)&sg.ws[cur][cL][kk];
            ulonglong2 w1, w2;
            if (NG == 3) {
                w1 = *(const ulonglong2*)&sg.ws[cur][16 + cL][kk];
                w2 = *(const ulonglong2*)&sg.ws[cur][32 + cL][kk];
            }
            #pragma unroll
            for (int i = 0; i < 8; i++) {
                ulonglong2 h = *(const ulonglong2*)&sg.hs[cur][rG*8 + i][kk];
                a0[i] = fma2(h.x, w0.x, a0[i]);
                a0[i] = fma2(h.y, w0.y, a0[i]);
                if (NG == 3) {
                    a1[i] = fma2(h.x, w1.x, a1[i]);
                    a1[i] = fma2(h.y, w1.y, a1[i]);
                    a2[i] = fma2(h.x, w2.x, a2[i]);
                    a2[i] = fma2(h.y, w2.y, a2[i]);
                }
            }
        }
        barg(slice);
    }
#undef GLD
#undef GST
}

// ---------------- GEMM unit: 64 rows x 16 cols x 3 gates -> raw sums to out planes ----------------
__device__ void gemm3_unit(const float* __restrict__ A, int lda,
                           const float* __restrict__ W, int K,
                           float* __restrict__ out,   // [3][B][H] planes
                           int rowBase, int colBase, SmAll& sm)
{
    const int tid   = threadIdx.x;
    const int t1    = tid & 127;
    const int slice = tid >> 7;
    const int cL    = t1 & 15;
    const int rG    = t1 >> 4;

    u64 a0[8] = {0,0,0,0,0,0,0,0};
    u64 a1[8] = {0,0,0,0,0,0,0,0};
    u64 a2[8] = {0,0,0,0,0,0,0,0};

    const int Kh = K >> 2;
    gemm_pipe<3>(A, lda, W, K, slice*Kh, Kh, rowBase, colBase,
                 a0, a1, a2, sm.sl[slice], slice);

    __syncthreads();
    if (slice) {
        u64* d = sm.comb[slice-1][t1];
        #pragma unroll
        for (int i = 0; i < 8; i++) {
            d[i]      = a0[i];
            d[8 + i]  = a1[i];
            d[16 + i] = a2[i];
        }
    }
    __syncthreads();
    if (slice == 0) {
        #pragma unroll
        for (int s = 0; s < 3; s++) {
            const u64* d = sm.comb[s][t1];
            #pragma unroll
            for (int i = 0; i < 8; i++) {
                a0[i] = add2(a0[i], d[i]);
                a1[i] = add2(a1[i], d[8 + i]);
                a2[i] = add2(a2[i], d[16 + i]);
            }
        }
        const int col = colBase + cL;
        #pragma unroll
        for (int i = 0; i < 8; i++) {
            size_t o = (size_t)(rowBase + rG*8 + i)*HDIM + col;
            out[o]              = red2(a0[i]);
            out[(size_t)BH + o] = red2(a1[i]);
            out[(size_t)2*BH+ o]= red2(a2[i]);
        }
    }
    __syncthreads();
}

// ---------------- linear unit: 64 x 16, out = A @ W.T + b ----------------
__device__ void gemm1_unit(const float* __restrict__ A, int lda,
                           const float* __restrict__ W, int K,
                           const float* __restrict__ bias,
                           float* __restrict__ out,   // [B][H]
                           int rowBase, int colBase, SmAll& sm)
{
    const int tid   = threadIdx.x;
    const int t1    = tid & 127;
    const int slice = tid >> 7;
    const int cL    = t1 & 15;
    const int rG    = t1 >> 4;

    u64 a0[8] = {0,0,0,0,0,0,0,0};
    u64 d1[8] = {0,0,0,0,0,0,0,0};
    u64 d2[8] = {0,0,0,0,0,0,0,0};

    const int Kh = K >> 2;
    gemm_pipe<1>(A, lda, W, K, slice*Kh, Kh, rowBase, colBase,
                 a0, d1, d2, sm.sl[slice], slice);

    __syncthreads();
    if (slice) {
        u64* d = sm.comb[slice-1][t1];
        #pragma unroll
        for (int i = 0; i < 8; i++) d[i] = a0[i];
    }
    __syncthreads();
    if (slice == 0) {
        #pragma unroll
        for (int s = 0; s < 3; s++) {
            const u64* d = sm.comb[s][t1];
            #pragma unroll
            for (int i = 0; i < 8; i++) a0[i] = add2(a0[i], d[i]);
        }
        const int col = colBase + cL;
        float bb = bias[col];
        #pragma unroll
        for (int i = 0; i < 8; i++)
            out[(size_t)(rowBase + rG*8 + i)*HDIM + col] = red2(a0[i]) + bb;
    }
    __syncthreads();
}

// ---------------- zero a 64x16x3 region of a gate-sum buffer ----------------
__device__ void zero3(float* __restrict__ buf, int rowBase, int colBase)
{
    for (int i = threadIdx.x; i < 3*64*16; i += NTHR) {
        int g = i >> 10;
        int rem = i & 1023;
        int row = rem >> 4;
        int col = rem & 15;
        buf[(size_t)g*BH + (size_t)(rowBase + row)*HDIM + colBase + col] = 0.f;
    }
    __syncthreads();
}

// ---------------- GRU epilogue: one batch row, 512 threads = 512 cols ----------------
__device__ void gru_epi(int b,
                        const float* __restrict__ gi,   // [3][B][H] or null (L0)
                        const float* __restrict__ gh,   // [3][B][H]
                        const float* __restrict__ bih,
                        const float* __restrict__ bhh,
                        const float* __restrict__ hprev, // [B][H] or null
                        const float* __restrict__ xrow,  // L0 only: x + b*TIN*2 + s*2
                        const float* __restrict__ Wih2,  // L0 only: [3H][2]
                        float* __restrict__ hout)
{
    const int c = threadIdx.x;
    const size_t o = (size_t)b*HDIM + c;

    float gir, giz, gin;
    if (gi) {
        gir = gi[o];
        giz = gi[(size_t)BH + o];
        gin = gi[(size_t)2*BH + o];
    } else {
        float x0 = xrow[0], x1 = xrow[1];
        gir = x0*Wih2[(size_t)(0*HDIM + c)*2] + x1*Wih2[(size_t)(0*HDIM + c)*2 + 1];
        giz = x0*Wih2[(size_t)(1*HDIM + c)*2] + x1*Wih2[(size_t)(1*HDIM + c)*2 + 1];
        gin = x0*Wih2[(size_t)(2*HDIM + c)*2] + x1*Wih2[(size_t)(2*HDIM + c)*2 + 1];
    }
    float ghr = gh[o];
    float ghz = gh[(size_t)BH + o];
    float ghn = gh[(size_t)2*BH + o];

    float r = 1.f / (1.f + expf(-(gir + ghr + bih[c] + bhh[c])));
    float z = 1.f / (1.f + expf(-(giz + ghz + bih[HDIM+c] + bhh[HDIM+c])));
    float n = tanhf(gin + bih[2*HDIM+c] + r * (ghn + bhh[2*HDIM+c]));
    float hp = hprev ? hprev[o] : 0.f;
    hout[o] = (1.f - z) * n + z * hp;
}

// ---------------- attention for one batch row (512 threads) ----------------
__device__ void attn_row(int b, int t,
                         const float* __restrict__ query,
                         const float* __restrict__ enc,
                         const float* __restrict__ emb,
                         const int*   __restrict__ tokp,
                         float* __restrict__ rnn_in,
                         float* __restrict__ att_out,
                         SmA& sa)
{
    const int tid = threadIdx.x;
    const int warp = tid >> 5, lane = tid & 31;

    sa.q[tid] = query[(size_t)b*HDIM + tid];
    __syncthreads();

    const float* encb = enc + (size_t)b*HDIM;
    for (int tt = warp; tt < TIN; tt += 16) {
        const float* e = encb + (size_t)tt*BH;
        float s = 0.f;
        #pragma unroll
        for (int k = lane; k < HDIM; k += 32) s = fmaf(sa.q[k], e[k], s);
        #pragma unroll
        for (int o = 16; o; o >>= 1) s += __shfl_xor_sync(0xffffffffu, s, o);
        if (!lane) sa.sc[tt] = s;
    }
    __syncthreads();

    if (tid < 256) {
        float v = sa.sc[tid];
        float m = v;
        #pragma unroll
        for (int o = 16; o; o >>= 1) m = fmaxf(m, __shfl_xor_sync(0xffffffffu, m, o));
        if (!lane) sa.red[warp] = m;
    }
    __syncthreads();
    float gm = sa.red[0];
    #pragma unroll
    for (int i = 1; i < 8; i++) gm = fmaxf(gm, sa.red[i]);
    __syncthreads();
    if (tid < 256) {
        float v = sa.sc[tid];
        float e = expf(v - gm);
        float s = e;
        #pragma unroll
        for (int o = 16; o; o >>= 1) s += __shfl_xor_sync(0xffffffffu, s, o);
        if (!lane) sa.red[8 + warp] = s;
        sa.sc[tid] = e;
    }
    __syncthreads();
    float tot = 0.f;
    #pragma unroll
    for (int i = 0; i < 8; i++) tot += sa.red[8 + i];
    float inv_tot = 1.f / tot;
    if (tid < 256) {
        float w = sa.sc[tid] * inv_tot;
        sa.sc[tid] = w;
        att_out[(size_t)b*MLEN*TIN + (size_t)t*TIN + tid] = w;
    }
    __syncthreads();

    float c = 0.f;
    #pragma unroll 4
    for (int tt = 0; tt < TIN; tt++)
        c = fmaf(sa.sc[tt], encb[(size_t)tt*BH + tid], c);
    float* rb = rnn_in + (size_t)b*1024;
    rb[512 + tid] = c;

    const int tk = tokp[b];
    rb[tid] = emb[(size_t)tk*HDIM + tid];
    __syncthreads();
}

// ---------------- logits + argmax for one batch row (512 threads) ----------------
__device__ void logits_row(int b, int t,
                           const float* __restrict__ g1,
                           const float* __restrict__ outW,
                           const float* __restrict__ outb,
                           float* __restrict__ vec_out,
                           int* __restrict__ tok_next,
                           SmL& sl)
{
    const int tid = threadIdx.x;
    const int warp = tid >> 5, lane = tid & 31;

    sl.hrow[tid] = g1[(size_t)b*HDIM + tid];
    __syncthreads();

    for (int v = warp; v < VOC; v += 16) {
        const float* wrow = outW + (size_t)v*HDIM;
        float s = 0.f;
        #pragma unroll
        for (int k = lane; k < HDIM; k += 32) s = fmaf(sl.hrow[k], wrow[k], s);
        #pragma unroll
        for (int o = 16; o; o >>= 1) s += __shfl_xor_sync(0xffffffffu, s, o);
        if (!lane) {
            s += outb[v];
            sl.lg[v] = s;
            vec_out[(size_t)b*MLEN*VOC + (size_t)t*VOC + v] = s;
        }
    }
    __syncthreads();
    if (tid == 0) {
        int best = 0; float bv = sl.lg[0];
        #pragma unroll
        for (int v = 1; v < VOC; v++)
            if (sl.lg[v] > bv) { bv = sl.lg[v]; best = v; }
        tok_next[b] = best;
    }
    __syncthreads();
}

// ---------------- init kernel ----------------
__global__ void init_kernel()
{
    if (threadIdx.x == 0) { g_arrive = 0; g_release = 0; }
    g_tok[threadIdx.x] = 0;
}

// ---------------- persistent megakernel ----------------
__global__ void __launch_bounds__(NTHR, 1)
mega_kernel(const float* __restrict__ x,
            const float* __restrict__ emb,
            const float* __restrict__ eWih0, const float* __restrict__ eWhh0,
            const float* __restrict__ ebih0, const float* __restrict__ ebhh0,
            const float* __restrict__ eWih1, const float* __restrict__ eWhh1,
            const float* __restrict__ ebih1, const float* __restrict__ ebhh1,
            const float* __restrict__ dWih0, const float* __restrict__ dWhh0,
            const float* __restrict__ dbih0, const float* __restrict__ dbhh0,
            const float* __restrict__ dWih1, const float* __restrict__ dWhh1,
            const float* __restrict__ dbih1, const float* __restrict__ dbhh1,
            const float* __restrict__ qW,    const float* __restrict__ qb,
            const float* __restrict__ outW,  const float* __restrict__ outb,
            float* __restrict__ vec_out,
            float* __restrict__ hid_out,
            float* __restrict__ att_out)
{
    extern __shared__ unsigned char smraw[];
    SmAll& sm = *reinterpret_cast<SmAll*>(smraw);
    unsigned phase = 0;
    const int bid = blockIdx.x;

    // ================= encoder =================
    // superstep s: Phase A = GEMMs (L0-hid(s), L1-hid(s-1), L1-in(s-1)), Phase B = epilogues
    for (int s = 0; s <= TIN; s++) {
        // ---- Phase A: 192 gemm units ----
        for (int u = bid; u < 192; u += NBLK) {
            int grp  = u >> 6;
            int tile = u & 63;
            int rowBase = (tile >> 5) * 64;
            int colBase = (tile & 31) * 16;
            if (grp == 0) {            // L0 hidden sums for step s
                if (s < TIN) {
                    if (s == 0) zero3(g_ghE0, rowBase, colBase);
                    else gemm3_unit(g_y0 + (size_t)(s-1)*BH, HDIM, eWhh0, HDIM,
                                    g_ghE0, rowBase, colBase, sm);
                }
            } else if (grp == 1) {     // L1 hidden sums for step s-1
                if (s >= 1) {
                    int t = s - 1;
                    if (t == 0) zero3(g_ghE1, rowBase, colBase);
                    else gemm3_unit(g_enc + (size_t)(t-1)*BH, HDIM, eWhh1, HDIM,
                                    g_ghE1, rowBase, colBase, sm);
                }
            } else {                   // L1 input sums for step s-1
                if (s >= 1) {
                    int t = s - 1;
                    gemm3_unit(g_y0 + (size_t)t*BH, HDIM, eWih1, HDIM,
                               g_giE1, rowBase, colBase, sm);
                }
            }
        }
        gsync(phase);

        // ---- Phase B: 256 epilogue units (one row each) ----
        for (int u = bid; u < 256; u += NBLK) {
            if (u < 128) {
                if (s < TIN) {
                    const float* hprev = s ? (g_y0 + (size_t)(s-1)*BH) : nullptr;
                    gru_epi(u, nullptr, g_ghE0, ebih0, ebhh0, hprev,
                            x + (size_t)u*TIN*2 + (size_t)s*2, eWih0,
                            g_y0 + (size_t)s*BH);
                }
            } else {
                if (s >= 1) {
                    int t = s - 1;
                    int b = u - 128;
                    const float* hprev = t ? (g_enc + (size_t)(t-1)*BH) : nullptr;
                    gru_epi(b, g_giE1, g_ghE1, ebih1, ebhh1, hprev,
                            nullptr, nullptr, g_enc + (size_t)t*BH);
                }
            }
        }
        gsync(phase);
    }

    // ================= decoder =================
    // pre: query(0)
    for (int u = bid; u < 64; u += NBLK) {
        int rowBase = (u >> 5) * 64;
        int colBase = (u & 31) * 16;
        gemm1_unit(g_enc + (size_t)(TIN-1)*BH, HDIM, qW, HDIM, qb,
                   g_q, rowBase, colBase, sm);
    }
    gsync(phase);

    for (int t = 0; t < MLEN; t++) {
        const float* h0prev = t ? (g_h0 + (size_t)(t-1)*BH) : (g_y0  + (size_t)(TIN-1)*BH);
        const float* h1prev = t ? (g_h1 + (size_t)(t-1)*BH) : (g_enc + (size_t)(TIN-1)*BH);

        // Ph_b: attention
        for (int u = bid; u < BSZ; u += NBLK)
            attn_row(u, t, g_q + (size_t)t*BH, g_enc, emb,
                     g_tok + (size_t)t*BSZ, g_rnn + (size_t)t*B2H, att_out, sm.a);
        gsync(phase);

        // Ph_c: gru0 GEMMs (input K=1024 + hidden K=512), 128 units
        for (int u = bid; u < 128; u += NBLK) {
            int grp  = u >> 6;
            int tile = u & 63;
            int rowBase = (tile >> 5) * 64;
            int colBase = (tile & 31) * 16;
            if (grp == 0)
                gemm3_unit(g_rnn + (size_t)t*B2H, 2*HDIM, dWih0, 2*HDIM,
                           g_gi0, rowBase, colBase, sm);
            else
                gemm3_unit(h0prev, HDIM, dWhh0, HDIM,
                           g_gh0, rowBase, colBase, sm);
        }
        gsync(phase);

        // Ph_d: gru0 epilogue
        for (int u = bid; u < 128; u += NBLK)
            gru_epi(u, g_gi0, g_gh0, dbih0, dbhh0, h0prev,
                    nullptr, nullptr, g_h0 + (size_t)t*BH);
        gsync(phase);

        // Ph_e: gru1 GEMMs, 128 units
        for (int u = bid; u < 128; u += NBLK) {
            int grp  = u >> 6;
            int tile = u & 63;
            int rowBase = (tile >> 5) * 64;
            int colBase = (tile & 31) * 16;
            if (grp == 0)
                gemm3_unit(g_h0 + (size_t)t*BH, HDIM, dWih1, HDIM,
                           g_gi1, rowBase, colBase, sm);
            else
                gemm3_unit(h1prev, HDIM, dWhh1, HDIM,
                           g_gh1, rowBase, colBase, sm);
        }
        gsync(phase);

        // Ph_f: gru1 epilogue
        for (int u = bid; u < 128; u += NBLK)
            gru_epi(u, g_gi1, g_gh1, dbih1, dbhh1, h1prev,
                    nullptr, nullptr, g_h1 + (size_t)t*BH);
        gsync(phase);

        // Ph_g: logits+argmax (0..127) and next-step query (128..191)
        for (int u = bid; u < 192; u += NBLK) {
            if (u < 128) {
                logits_row(u, t, g_h1 + (size_t)t*BH, outW, outb,
                           vec_out, g_tok + (size_t)(t+1)*BSZ, sm.l);
            } else if (t + 1 < MLEN) {
                int tile = u - 128;
                int rowBase = (tile >> 5) * 64;
                int colBase = (tile & 31) * 16;
                gemm1_unit(g_h1 + (size_t)t*BH, HDIM, qW, HDIM, qb,
                           g_q + (size_t)(t+1)*BH, rowBase, colBase, sm);
            }
        }
        gsync(phase);
    }

    // ---------- final hidden copy ----------
    for (int i = bid*NTHR + threadIdx.x; i < BH; i += NBLK*NTHR) {
        hid_out[i]      = g_h0[(size_t)(MLEN-1)*BH + i];
        hid_out[BH + i] = g_h1[(size_t)(MLEN-1)*BH + i];
    }
}

// ---------------- host ----------------
extern "C" void kernel_launch(void* const* d_in, const int* in_sizes, int n_in,
                              void* d_out, int out_size)
{
    const float* x     = (const float*)d_in[0];
    const float* emb   = (const float*)d_in[1];
    const float* eWih0 = (const float*)d_in[2];
    const float* eWhh0 = (const float*)d_in[3];
    const float* ebih0 = (const float*)d_in[4];
    const float* ebhh0 = (const float*)d_in[5];
    const float* eWih1 = (const float*)d_in[6];
    const float* eWhh1 = (const float*)d_in[7];
    const float* ebih1 = (const float*)d_in[8];
    const float* ebhh1 = (const float*)d_in[9];
    const float* dWih0 = (const float*)d_in[10];
    const float* dWhh0 = (const float*)d_in[11];
    const float* dbih0 = (const float*)d_in[12];
    const float* dbhh0 = (const float*)d_in[13];
    const float* dWih1 = (const float*)d_in[14];
    const float* dWhh1 = (const float*)d_in[15];
    const float* dbih1 = (const float*)d_in[16];
    const float* dbhh1 = (const float*)d_in[17];
    const float* qW    = (const float*)d_in[18];
    const float* qb    = (const float*)d_in[19];
    const float* outW  = (const float*)d_in[20];
    const float* outb  = (const float*)d_in[21];

    float* out     = (float*)d_out;
    float* vec_out = out;
    float* hid_out = out + (size_t)BSZ*MLEN*VOC;
    float* att_out = hid_out + 2*BH;

    static int smem_set = 0;
    if (!smem_set) {
        cudaFuncSetAttribute(mega_kernel,
                             cudaFuncAttributeMaxDynamicSharedMemorySize,
                             (int)sizeof(SmAll));
        smem_set = 1;
    }

    init_kernel<<<1, BSZ>>>();
    mega_kernel<<<NBLK, NTHR, sizeof(SmAll)>>>(x, emb,
                                eWih0, eWhh0, ebih0, ebhh0,
                                eWih1, eWhh1, ebih1, ebhh1,
                                dWih0, dWhh0, dbih0, dbhh0,
                                dWih1, dWhh1, dbih1, dbhh1,
                                qW, qb, outW, outb,
                                vec_out, hid_out, att_out);
}

// round 17
// speedup vs baseline: 1.5076x; 1.5076x over previous
#include <cuda_runtime.h>
#include <cuda_bf16.h>
#include <math.h>

#define HDIM 512
#define BSZ  128
#define TIN  256
#define MLEN 128
#define VOC  32
#define BH   (BSZ*HDIM)
#define B2H  (BSZ*2*HDIM)
#define NBLK 148
#define NTHR 256

typedef __nv_bfloat16 bf16;

// ---------------- fp32 state ----------------
__device__ float g_y0[TIN*BH];
__device__ float g_enc[TIN*BH];
__device__ float g_q[MLEN*BH];
__device__ float g_h0[MLEN*BH];
__device__ float g_h1[MLEN*BH];
__device__ int   g_tok[(MLEN+1)*BSZ];
__device__ unsigned g_arrive;
__device__ volatile unsigned g_release;

// ---------------- bf16 hi/lo activation planes ----------------
__device__ bf16 g_y0h[TIN*BH],  g_y0l[TIN*BH];
__device__ bf16 g_ench[TIN*BH], g_encl[TIN*BH];
__device__ bf16 g_rnnh[MLEN*B2H], g_rnnl[MLEN*B2H];
__device__ bf16 g_h0h[MLEN*BH], g_h0l[MLEN*BH];
__device__ bf16 g_h1h[MLEN*BH], g_h1l[MLEN*BH];

// ---------------- bf16 hi/lo weight planes (split once per launch) ----------------
#define SZ3HH (3*HDIM*HDIM)
#define OW_EWHH0 ((size_t)0)
#define OW_EWIH1 (OW_EWHH0 + SZ3HH)
#define OW_EWHH1 (OW_EWIH1 + SZ3HH)
#define OW_DWIH0 (OW_EWHH1 + SZ3HH)
#define OW_DWHH0 (OW_DWIH0 + (size_t)3*HDIM*2*HDIM)
#define OW_DWIH1 (OW_DWHH0 + SZ3HH)
#define OW_DWHH1 (OW_DWIH1 + SZ3HH)
#define OW_QW    (OW_DWHH1 + SZ3HH)
#define NWTOT    (OW_QW + (size_t)HDIM*HDIM)
__device__ bf16 g_wh[NWTOT];
__device__ bf16 g_wl[NWTOT];

// ---------------- shared memory ----------------
struct __align__(16) SmG {
    bf16 As[2][2][64][72];   // [buf][hi/lo][row][k]  36864 B
    bf16 Bs[2][2][48][72];   // [buf][hi/lo][n(gate*16+c)][k]  27648 B
};
struct SmA { float q[HDIM]; float sc[TIN]; float red[16]; };
struct SmL { float hrow[HDIM]; float lg[VOC]; };
union SmAll { SmG g; SmA a; SmL l; };

// ---------------- helpers ----------------
__device__ __forceinline__ void splitf(float v, bf16& h, bf16& l)
{
    h = __float2bfloat16(v);
    l = __float2bfloat16(v - __bfloat162float(h));
}

#define MMA_BF16(c, A0,A1,A2,A3, B0,B1)                                      \
    asm volatile("mma.sync.aligned.m16n8k16.row.col.f32.bf16.bf16.f32 "      \
        "{%0,%1,%2,%3}, {%4,%5,%6,%7}, {%8,%9}, {%0,%1,%2,%3};"              \
        : "+f"((c)[0]), "+f"((c)[1]), "+f"((c)[2]), "+f"((c)[3])             \
        : "r"(A0), "r"(A1), "r"(A2), "r"(A3), "r"(B0), "r"(B1))

// ---------------- software grid barrier ----------------
__device__ __forceinline__ void gsync(unsigned &phase)
{
    __threadfence();
    __syncthreads();
    phase++;
    if (threadIdx.x == 0) {
        unsigned p = phase;
        unsigned old = atomicAdd(&g_arrive, 1u);
        if (old == p * (unsigned)NBLK - 1u) {
            g_release = p;
        } else {
            while (g_release < p) { }
        }
        __threadfence();
    }
    __syncthreads();
}

// ---------------- split-bf16 mma GEMM core ----------------
// Tile: 64 rows x 16 cols x NG gates. K multiple of 64. 256 threads.
// Warp w: mf = w>>1 (16-row frag), nh = w&1 (8-col half).
// Accumulates into cr/cz/cn (gate 0/1/2), fp32 frags of 4.
template<int NG>
__device__ __forceinline__ void mma_gemm(
    const bf16* __restrict__ Ah, const bf16* __restrict__ Al, int lda,
    const bf16* __restrict__ Wh, const bf16* __restrict__ Wl, int ldw,
    int K, int rowBase, int colBase,
    float (&cr)[4], float (&cz)[4], float (&cn)[4],
    SmG& sg)
{
    const int tid  = threadIdx.x;
    const int lane = tid & 31, w = tid >> 5;
    const int mf = w >> 1, nh = w & 1;

    // A fill: 512 uint4/chunk/matrix, 2 per thread
    const int av0 = tid*2, av1 = tid*2 + 1;
    const int ar0 = av0 >> 3, ak0 = (av0 & 7) * 8;
    const int ar1 = av1 >> 3, ak1 = (av1 & 7) * 8;
    const size_t aoff0 = (size_t)(rowBase + ar0)*lda + ak0;
    const size_t aoff1 = (size_t)(rowBase + ar1)*lda + ak1;

    // B fill: NG3: 384 uint4/matrix (rows 0..47); NG1: 128 (rows 0..15)
    const int br0 = tid >> 3,        bk0 = (tid & 7) * 8;
    const int br1 = (tid + 256) >> 3, bk1 = (tid & 7) * 8;
    const bool bok0 = (NG == 3) ? true : (tid < 128);
    const bool bok1 = (NG == 3) && (tid < 128);
    size_t boff0 = 0, boff1 = 0;
    if (bok0) boff0 = (size_t)((br0 >> 4)*HDIM + colBase + (br0 & 15))*ldw + bk0;
    if (bok1) boff1 = (size_t)((br1 >> 4)*HDIM + colBase + (br1 & 15))*ldw + bk1;

    const int nch = K >> 6;
    uint4 pAh0, pAh1, pAl0, pAl1, pBh0, pBh1, pBl0, pBl1;

#define GLDM(c) do { size_t k0_ = (size_t)(c) << 6;                          \
        pAh0 = *(const uint4*)(Ah + aoff0 + k0_);                            \
        pAh1 = *(const uint4*)(Ah + aoff1 + k0_);                            \
        pAl0 = *(const uint4*)(Al + aoff0 + k0_);                            \
        pAl1 = *(const uint4*)(Al + aoff1 + k0_);                            \
        if (bok0) { pBh0 = *(const uint4*)(Wh + boff0 + k0_);                \
                    pBl0 = *(const uint4*)(Wl + boff0 + k0_); }              \
        if (bok1) { pBh1 = *(const uint4*)(Wh + boff1 + k0_);                \
                    pBl1 = *(const uint4*)(Wl + boff1 + k0_); }              \
    } while (0)
#define GSTM(b) do {                                                         \
        *(uint4*)&sg.As[b][0][ar0][ak0] = pAh0;                              \
        *(uint4*)&sg.As[b][0][ar1][ak1] = pAh1;                              \
        *(uint4*)&sg.As[b][1][ar0][ak0] = pAl0;                              \
        *(uint4*)&sg.As[b][1][ar1][ak1] = pAl1;                              \
        if (bok0) { *(uint4*)&sg.Bs[b][0][br0][bk0] = pBh0;                  \
                    *(uint4*)&sg.Bs[b][1][br0][bk0] = pBl0; }                \
        if (bok1) { *(uint4*)&sg.Bs[b][0][br1][bk1] = pBh1;                  \
                    *(uint4*)&sg.Bs[b][1][br1][bk1] = pBl1; }                \
    } while (0)

    GLDM(0); GSTM(0);
    if (nch > 1) GLDM(1);
    __syncthreads();

    const int arow = mf*16 + (lane >> 2);
    const int acol = (lane & 3) * 2;
    const int bn   = nh*8 + (lane >> 2);

    for (int c = 0; c < nch; c++) {
        const int cur = c & 1;
        if (c + 1 < nch) GSTM(cur ^ 1);
        if (c + 2 < nch) GLDM(c + 2);
        #pragma unroll
        for (int kk = 0; kk < 64; kk += 16) {
            unsigned ah0 = *(const unsigned*)&sg.As[cur][0][arow    ][kk + acol    ];
            unsigned ah1 = *(const unsigned*)&sg.As[cur][0][arow + 8][kk + acol    ];
            unsigned ah2 = *(const unsigned*)&sg.As[cur][0][arow    ][kk + acol + 8];
            unsigned ah3 = *(const unsigned*)&sg.As[cur][0][arow + 8][kk + acol + 8];
            unsigned al0 = *(const unsigned*)&sg.As[cur][1][arow    ][kk + acol    ];
            unsigned al1 = *(const unsigned*)&sg.As[cur][1][arow + 8][kk + acol    ];
            unsigned al2 = *(const unsigned*)&sg.As[cur][1][arow    ][kk + acol + 8];
            unsigned al3 = *(const unsigned*)&sg.As[cur][1][arow + 8][kk + acol + 8];
            #pragma unroll
            for (int g = 0; g < NG; g++) {
                unsigned bh0 = *(const unsigned*)&sg.Bs[cur][0][g*16 + bn][kk + acol    ];
                unsigned bh1 = *(const unsigned*)&sg.Bs[cur][0][g*16 + bn][kk + acol + 8];
                unsigned bl0 = *(const unsigned*)&sg.Bs[cur][1][g*16 + bn][kk + acol    ];
                unsigned bl1 = *(const unsigned*)&sg.Bs[cur][1][g*16 + bn][kk + acol + 8];
                float* cc = (g == 0) ? cr : (g == 1) ? cz : cn;
                MMA_BF16(cc, ah0, ah1, ah2, ah3, bh0, bh1);   // Ahi*Bhi
                MMA_BF16(cc, al0, al1, al2, al3, bh0, bh1);   // Alo*Bhi
                MMA_BF16(cc, ah0, ah1, ah2, ah3, bl0, bl1);   // Ahi*Blo
            }
        }
        __syncthreads();
    }
#undef GLDM
#undef GSTM
}

// ---------------- fused GRU unit: 64 rows x 16 cols, hidden+input GEMM + epilogue ----------------
__device__ void gru_unit(
    const float* __restrict__ hprevF,                    // fp32 hprev or null
    const bf16* __restrict__ Hh, const bf16* __restrict__ Hl,   // hprev bf16 or null
    size_t whhOff, const float* __restrict__ bhh,
    const bf16* __restrict__ Xh, const bf16* __restrict__ Xl, int ldx, int KIN,
    size_t wihOff, const float* __restrict__ bih,
    const float* __restrict__ x2, const float* __restrict__ Wih2, int xstep, // L0 path
    float* __restrict__ houtF, bf16* __restrict__ houtH, bf16* __restrict__ houtL,
    int rowBase, int colBase, SmG& sg)
{
    float cr[4]  = {0.f,0.f,0.f,0.f};
    float cz[4]  = {0.f,0.f,0.f,0.f};
    float cnh[4] = {0.f,0.f,0.f,0.f};
    float cni[4] = {0.f,0.f,0.f,0.f};

    if (Hh)
        mma_gemm<3>(Hh, Hl, HDIM, g_wh + whhOff, g_wl + whhOff, HDIM, HDIM,
                    rowBase, colBase, cr, cz, cnh, sg);
    if (Xh)
        mma_gemm<3>(Xh, Xl, ldx, g_wh + wihOff, g_wl + wihOff, KIN, KIN,
                    rowBase, colBase, cr, cz, cni, sg);

    const int lane = threadIdx.x & 31, w = threadIdx.x >> 5;
    const int mf = w >> 1, nh = w & 1;
    const int m0 = rowBase + mf*16 + (lane >> 2);
    const int n0 = colBase + nh*8 + (lane & 3)*2;

    #pragma unroll
    for (int j = 0; j < 4; j++) {
        const int row = m0 + (j >> 1)*8;
        const int col = n0 + (j & 1);
        float sr = cr[j], sz = cz[j], snh = cnh[j], sni = cni[j];
        if (x2) {
            float x0 = x2[(size_t)row*(TIN*2) + (size_t)xstep*2];
            float x1 = x2[(size_t)row*(TIN*2) + (size_t)xstep*2 + 1];
            sr  += x0*Wih2[(size_t)(0*HDIM+col)*2] + x1*Wih2[(size_t)(0*HDIM+col)*2+1];
            sz  += x0*Wih2[(size_t)(1*HDIM+col)*2] + x1*Wih2[(size_t)(1*HDIM+col)*2+1];
            sni += x0*Wih2[(size_t)(2*HDIM+col)*2] + x1*Wih2[(size_t)(2*HDIM+col)*2+1];
        }
        float r = 1.f / (1.f + expf(-(sr + bih[col] + bhh[col])));
        float z = 1.f / (1.f + expf(-(sz + bih[HDIM+col] + bhh[HDIM+col])));
        float n = tanhf(sni + bih[2*HDIM+col] + r * (snh + bhh[2*HDIM+col]));
        float hp = hprevF ? hprevF[(size_t)row*HDIM + col] : 0.f;
        float h = (1.f - z) * n + z * hp;
        size_t o = (size_t)row*HDIM + col;
        houtF[o] = h;
        splitf(h, houtH[o], houtL[o]);
    }
    __syncthreads();
}

// ---------------- query unit: 64 x 16, out = A @ qW.T + qb (fp32 out) ----------------
__device__ void query_unit(const bf16* __restrict__ Ah, const bf16* __restrict__ Al,
                           const float* __restrict__ qb, float* __restrict__ out,
                           int rowBase, int colBase, SmG& sg)
{
    float c0[4] = {0.f,0.f,0.f,0.f};
    float d1[4] = {0.f,0.f,0.f,0.f};
    float d2[4] = {0.f,0.f,0.f,0.f};
    mma_gemm<1>(Ah, Al, HDIM, g_wh + OW_QW, g_wl + OW_QW, HDIM, HDIM,
                rowBase, colBase, c0, d1, d2, sg);

    const int lane = threadIdx.x & 31, w = threadIdx.x >> 5;
    const int mf = w >> 1, nh = w & 1;
    const int m0 = rowBase + mf*16 + (lane >> 2);
    const int n0 = colBase + nh*8 + (lane & 3)*2;
    #pragma unroll
    for (int j = 0; j < 4; j++) {
        const int row = m0 + (j >> 1)*8;
        const int col = n0 + (j & 1);
        out[(size_t)row*HDIM + col] = c0[j] + qb[col];
    }
    __syncthreads();
}

// ---------------- attention for one batch row (256 threads, fp32) ----------------
__device__ void attn_row(int b, int t,
                         const float* __restrict__ query,
                         const float* __restrict__ enc,
                         const float* __restrict__ emb,
                         const int*   __restrict__ tokp,
                         bf16* __restrict__ rnnh, bf16* __restrict__ rnnl,
                         float* __restrict__ att_out,
                         SmA& sa)
{
    const int tid = threadIdx.x;
    const int warp = tid >> 5, lane = tid & 31;

    sa.q[tid]       = query[(size_t)b*HDIM + tid];
    sa.q[256 + tid] = query[(size_t)b*HDIM + 256 + tid];
    __syncthreads();

    const float* encb = enc + (size_t)b*HDIM;
    for (int tt = warp; tt < TIN; tt += 8) {
        const float* e = encb + (size_t)tt*BH;
        float s = 0.f;
        #pragma unroll
        for (int k = lane; k < HDIM; k += 32) s = fmaf(sa.q[k], e[k], s);
        #pragma unroll
        for (int o = 16; o; o >>= 1) s += __shfl_xor_sync(0xffffffffu, s, o);
        if (!lane) sa.sc[tt] = s;
    }
    __syncthreads();

    float v = sa.sc[tid];
    float m = v;
    #pragma unroll
    for (int o = 16; o; o >>= 1) m = fmaxf(m, __shfl_xor_sync(0xffffffffu, m, o));
    if (!lane) sa.red[warp] = m;
    __syncthreads();
    float gm = sa.red[0];
    #pragma unroll
    for (int i = 1; i < 8; i++) gm = fmaxf(gm, sa.red[i]);
    __syncthreads();
    float e = expf(v - gm);
    float s = e;
    #pragma unroll
    for (int o = 16; o; o >>= 1) s += __shfl_xor_sync(0xffffffffu, s, o);
    if (!lane) sa.red[8 + warp] = s;
    __syncthreads();
    float tot = 0.f;
    #pragma unroll
    for (int i = 0; i < 8; i++) tot += sa.red[8 + i];
    float wv = e / tot;
    sa.sc[tid] = wv;
    att_out[(size_t)b*MLEN*TIN + (size_t)t*TIN + tid] = wv;
    __syncthreads();

    float c0 = 0.f, c1 = 0.f;
    #pragma unroll 4
    for (int tt = 0; tt < TIN; tt++) {
        float ww = sa.sc[tt];
        const float* e2 = encb + (size_t)tt*BH;
        c0 = fmaf(ww, e2[tid],       c0);
        c1 = fmaf(ww, e2[256 + tid], c1);
    }
    const size_t rbo = (size_t)b*1024;
    splitf(c0, rnnh[rbo + 512 + tid], rnnl[rbo + 512 + tid]);
    splitf(c1, rnnh[rbo + 768 + tid], rnnl[rbo + 768 + tid]);

    const int tk = tokp[b];
    float e0 = emb[(size_t)tk*HDIM + tid];
    float e1 = emb[(size_t)tk*HDIM + 256 + tid];
    splitf(e0, rnnh[rbo + tid],       rnnl[rbo + tid]);
    splitf(e1, rnnh[rbo + 256 + tid], rnnl[rbo + 256 + tid]);
    __syncthreads();
}

// ---------------- logits + argmax for one batch row (256 threads) ----------------
__device__ void logits_row(int b, int t,
                           const float* __restrict__ g1,
                           const float* __restrict__ outW,
                           const float* __restrict__ outb,
                           float* __restrict__ vec_out,
                           int* __restrict__ tok_next,
                           SmL& sl)
{
    const int tid = threadIdx.x;
    const int warp = tid >> 5, lane = tid & 31;

    sl.hrow[tid]       = g1[(size_t)b*HDIM + tid];
    sl.hrow[256 + tid] = g1[(size_t)b*HDIM + 256 + tid];
    __syncthreads();

    for (int v = warp; v < VOC; v += 8) {
        const float* wrow = outW + (size_t)v*HDIM;
        float s = 0.f;
        #pragma unroll
        for (int k = lane; k < HDIM; k += 32) s = fmaf(sl.hrow[k], wrow[k], s);
        #pragma unroll
        for (int o = 16; o; o >>= 1) s += __shfl_xor_sync(0xffffffffu, s, o);
        if (!lane) {
            s += outb[v];
            sl.lg[v] = s;
            vec_out[(size_t)b*MLEN*VOC + (size_t)t*VOC + v] = s;
        }
    }
    __syncthreads();
    if (tid == 0) {
        int best = 0; float bv = sl.lg[0];
        #pragma unroll
        for (int v = 1; v < VOC; v++)
            if (sl.lg[v] > bv) { bv = sl.lg[v]; best = v; }
        tok_next[b] = best;
    }
    __syncthreads();
}

// ---------------- weight split ----------------
__device__ void split_plane(const float* __restrict__ src, size_t n, size_t off)
{
    for (size_t i = (size_t)blockIdx.x*NTHR + threadIdx.x; i < n;
         i += (size_t)NBLK*NTHR)
        splitf(src[i], g_wh[off + i], g_wl[off + i]);
}

// ---------------- init kernel ----------------
__global__ void init_kernel()
{
    if (threadIdx.x == 0) { g_arrive = 0; g_release = 0; }
    g_tok[threadIdx.x] = 0;
}

// ---------------- persistent megakernel ----------------
__global__ void __launch_bounds__(NTHR, 1)
mega_kernel(const float* __restrict__ x,
            const float* __restrict__ emb,
            const float* __restrict__ eWih0, const float* __restrict__ eWhh0,
            const float* __restrict__ ebih0, const float* __restrict__ ebhh0,
            const float* __restrict__ eWih1, const float* __restrict__ eWhh1,
            const float* __restrict__ ebih1, const float* __restrict__ ebhh1,
            const float* __restrict__ dWih0, const float* __restrict__ dWhh0,
            const float* __restrict__ dbih0, const float* __restrict__ dbhh0,
            const float* __restrict__ dWih1, const float* __restrict__ dWhh1,
            const float* __restrict__ dbih1, const float* __restrict__ dbhh1,
            const float* __restrict__ qW,    const float* __restrict__ qb,
            const float* __restrict__ outW,  const float* __restrict__ outb,
            float* __restrict__ vec_out,
            float* __restrict__ hid_out,
            float* __restrict__ att_out)
{
    extern __shared__ unsigned char smraw[];
    SmAll& sm = *reinterpret_cast<SmAll*>(smraw);
    unsigned phase = 0;
    const int bid = blockIdx.x;

    // ---------- phase 0: split all weights into bf16 hi/lo planes ----------
    split_plane(eWhh0, SZ3HH, OW_EWHH0);
    split_plane(eWih1, SZ3HH, OW_EWIH1);
    split_plane(eWhh1, SZ3HH, OW_EWHH1);
    split_plane(dWih0, (size_t)3*HDIM*2*HDIM, OW_DWIH0);
    split_plane(dWhh0, SZ3HH, OW_DWHH0);
    split_plane(dWih1, SZ3HH, OW_DWIH1);
    split_plane(dWhh1, SZ3HH, OW_DWHH1);
    split_plane(qW, (size_t)HDIM*HDIM, OW_QW);
    gsync(phase);

    // ---------- encoder: L0[s] and L1[s-1] pipelined, 128 units, 1 gsync ----------
    for (int s = 0; s <= TIN; s++) {
        for (int u = bid; u < 128; u += NBLK) {
            int tile = u & 63;
            int rowBase = (tile >> 5) * 64;
            int colBase = (tile & 31) * 16;
            if (u < 64) {
                if (s < TIN) {
                    const float* hpf = s ? (g_y0 + (size_t)(s-1)*BH) : nullptr;
                    const bf16* hh = s ? (g_y0h + (size_t)(s-1)*BH) : nullptr;
                    const bf16* hl = s ? (g_y0l + (size_t)(s-1)*BH) : nullptr;
                    gru_unit(hpf, hh, hl, OW_EWHH0, ebhh0,
                             nullptr, nullptr, 0, 0, 0, ebih0,
                             x, eWih0, s,
                             g_y0 + (size_t)s*BH, g_y0h + (size_t)s*BH,
                             g_y0l + (size_t)s*BH,
                             rowBase, colBase, sm.g);
                }
            } else {
                if (s >= 1) {
                    int t = s - 1;
                    const float* hpf = t ? (g_enc + (size_t)(t-1)*BH) : nullptr;
                    const bf16* hh = t ? (g_ench + (size_t)(t-1)*BH) : nullptr;
                    const bf16* hl = t ? (g_encl + (size_t)(t-1)*BH) : nullptr;
                    gru_unit(hpf, hh, hl, OW_EWHH1, ebhh1,
                             g_y0h + (size_t)t*BH, g_y0l + (size_t)t*BH, HDIM, HDIM,
                             OW_EWIH1, ebih1,
                             nullptr, nullptr, 0,
                             g_enc + (size_t)t*BH, g_ench + (size_t)t*BH,
                             g_encl + (size_t)t*BH,
                             rowBase, colBase, sm.g);
                }
            }
        }
        gsync(phase);
    }

    // ---------- query(0) ----------
    for (int u = bid; u < 64; u += NBLK) {
        int rowBase = (u >> 5) * 64;
        int colBase = (u & 31) * 16;
        query_unit(g_ench + (size_t)(TIN-1)*BH, g_encl + (size_t)(TIN-1)*BH,
                   qb, g_q, rowBase, colBase, sm.g);
    }
    gsync(phase);

    // ---------- decoder ----------
    for (int t = 0; t < MLEN; t++) {
        const float* h0pf = t ? (g_h0 + (size_t)(t-1)*BH) : (g_y0  + (size_t)(TIN-1)*BH);
        const bf16*  h0ph = t ? (g_h0h + (size_t)(t-1)*BH) : (g_y0h + (size_t)(TIN-1)*BH);
        const bf16*  h0pl = t ? (g_h0l + (size_t)(t-1)*BH) : (g_y0l + (size_t)(TIN-1)*BH);
        const float* h1pf = t ? (g_h1 + (size_t)(t-1)*BH) : (g_enc + (size_t)(TIN-1)*BH);
        const bf16*  h1ph = t ? (g_h1h + (size_t)(t-1)*BH) : (g_ench + (size_t)(TIN-1)*BH);
        const bf16*  h1pl = t ? (g_h1l + (size_t)(t-1)*BH) : (g_encl + (size_t)(TIN-1)*BH);

        // Ph_b: attention
        for (int u = bid; u < BSZ; u += NBLK)
            attn_row(u, t, g_q + (size_t)t*BH, g_enc, emb,
                     g_tok + (size_t)t*BSZ,
                     g_rnnh + (size_t)t*B2H, g_rnnl + (size_t)t*B2H,
                     att_out, sm.a);
        gsync(phase);

        // Ph_c: gru0 (input K=1024 + hidden K=512), 64 units
        for (int u = bid; u < 64; u += NBLK) {
            int rowBase = (u >> 5) * 64;
            int colBase = (u & 31) * 16;
            gru_unit(h0pf, h0ph, h0pl, OW_DWHH0, dbhh0,
                     g_rnnh + (size_t)t*B2H, g_rnnl + (size_t)t*B2H, 2*HDIM, 2*HDIM,
                     OW_DWIH0, dbih0,
                     nullptr, nullptr, 0,
                     g_h0 + (size_t)t*BH, g_h0h + (size_t)t*BH, g_h0l + (size_t)t*BH,
                     rowBase, colBase, sm.g);
        }
        gsync(phase);

        // Ph_d: gru1, 64 units
        for (int u = bid; u < 64; u += NBLK) {
            int rowBase = (u >> 5) * 64;
            int colBase = (u & 31) * 16;
            gru_unit(h1pf, h1ph, h1pl, OW_DWHH1, dbhh1,
                     g_h0h + (size_t)t*BH, g_h0l + (size_t)t*BH, HDIM, HDIM,
                     OW_DWIH1, dbih1,
                     nullptr, nullptr, 0,
                     g_h1 + (size_t)t*BH, g_h1h + (size_t)t*BH, g_h1l + (size_t)t*BH,
                     rowBase, colBase, sm.g);
        }
        gsync(phase);

        // Ph_e: logits (128) + next query (64)
        for (int u = bid; u < 192; u += NBLK) {
            if (u < 128) {
                logits_row(u, t, g_h1 + (size_t)t*BH, outW, outb,
                           vec_out, g_tok + (size_t)(t+1)*BSZ, sm.l);
            } else if (t + 1 < MLEN) {
                int tile = u - 128;
                int rowBase = (tile >> 5) * 64;
                int colBase = (tile & 31) * 16;
                query_unit(g_h1h + (size_t)t*BH, g_h1l + (size_t)t*BH,
                           qb, g_q + (size_t)(t+1)*BH, rowBase, colBase, sm.g);
            }
        }
        gsync(phase);
    }

    // ---------- final hidden copy ----------
    for (int i = bid*NTHR + threadIdx.x; i < BH; i += NBLK*NTHR) {
        hid_out[i]      = g_h0[(size_t)(MLEN-1)*BH + i];
        hid_out[BH + i] = g_h1[(size_t)(MLEN-1)*BH + i];
    }
}

// ---------------- host ----------------
extern "C" void kernel_launch(void* const* d_in, const int* in_sizes, int n_in,
                              void* d_out, int out_size)
{
    const float* x     = (const float*)d_in[0];
    const float* emb   = (const float*)d_in[1];
    const float* eWih0 = (const float*)d_in[2];
    const float* eWhh0 = (const float*)d_in[3];
    const float* ebih0 = (const float*)d_in[4];
    const float* ebhh0 = (const float*)d_in[5];
    const float* eWih1 = (const float*)d_in[6];
    const float* eWhh1 = (const float*)d_in[7];
    const float* ebih1 = (const float*)d_in[8];
    const float* ebhh1 = (const float*)d_in[9];
    const float* dWih0 = (const float*)d_in[10];
    const float* dWhh0 = (const float*)d_in[11];
    const float* dbih0 = (const float*)d_in[12];
    const float* dbhh0 = (const float*)d_in[13];
    const float* dWih1 = (const float*)d_in[14];
    const float* dWhh1 = (const float*)d_in[15];
    const float* dbih1 = (const float*)d_in[16];
    const float* dbhh1 = (const float*)d_in[17];
    const float* qW    = (const float*)d_in[18];
    const float* qb    = (const float*)d_in[19];
    const float* outW  = (const float*)d_in[20];
    const float* outb  = (const float*)d_in[21];

    float* out     = (float*)d_out;
    float* vec_out = out;
    float* hid_out = out + (size_t)BSZ*MLEN*VOC;
    float* att_out = hid_out + 2*BH;

    static int smem_set = 0;
    if (!smem_set) {
        cudaFuncSetAttribute(mega_kernel,
                             cudaFuncAttributeMaxDynamicSharedMemorySize,
                             (int)sizeof(SmAll));
        smem_set = 1;
    }

    init_kernel<<<1, BSZ>>>();
    mega_kernel<<<NBLK, NTHR, sizeof(SmAll)>>>(x, emb,
                                eWih0, eWhh0, ebih0, ebhh0,
                                eWih1, eWhh1, ebih1, ebhh1,
                                dWih0, dWhh0, dbih0, dbhh0,
                                dWih1, dWhh1, dbih1, dbhh1,
                                qW, qb, outW, outb,
                                vec_out, hid_out, att_out);
}